// round 12
// baseline (speedup 1.0000x reference)
#include <cuda_runtime.h>
#include <math.h>
#include <stdint.h>

#define BB   4
#define SS   1024
#define DD   1024
#define HH   16
#define DK_  64
#define DV_  128
#define LL   3
#define FFN_ 4096
#define MM   (BB*SS)   // 4096 tokens

// ------------------------------------------------------------------
// Scratch buffers (static device allocations; no cudaMalloc allowed)
// ------------------------------------------------------------------
__device__ float g_h  [MM*DD];       // residual stream
__device__ float g_x  [MM*DD];       // LN output (tf32-rounded)
__device__ float g_q  [MM*DD];
__device__ float g_k  [MM*DD];
__device__ float g_v  [MM*2*DD];
__device__ float g_g  [MM*2*DD];     // gate pre-activation
__device__ float g_ao [MM*2*DD];     // gated attention output (tf32-rounded)
__device__ float g_ffn[MM*FFN_];     // FFN intermediate (tf32-rounded)
__device__ float g_sin[SS*32];
__device__ float g_cos[SS*32];
// tf32-rounded weight copies
__device__ float g_wq[LL*DD*DD];
__device__ float g_wk[LL*DD*DD];
__device__ float g_wv[LL*DD*2*DD];
__device__ float g_wg[LL*DD*2*DD];
__device__ float g_wo[LL*2*DD*DD];
__device__ float g_w1[LL*DD*FFN_];
__device__ float g_w2[LL*FFN_*DD];

// ------------------------------------------------------------------
// Helpers
// ------------------------------------------------------------------
__device__ __forceinline__ float gelu_tanh(float v) {
    const float c = 0.7978845608028654f;   // sqrt(2/pi)
    return 0.5f * v * (1.0f + tanhf(c * (v + 0.044715f * v * v * v)));
}

// round-to-nearest tf32 on a raw fp32 bit pattern (low 13 bits -> 0)
__device__ __forceinline__ uint32_t rtf(uint32_t bits) {
    uint32_t r;
    asm("cvt.rna.tf32.f32 %0, %1;" : "=r"(r) : "r"(bits));
    return r;
}
__device__ __forceinline__ float rtf_f(float x) {
    return __uint_as_float(rtf(__float_as_uint(x)));
}

__device__ __forceinline__ void cp16(void* smem_dst, const void* gsrc) {
    uint32_t a = (uint32_t)__cvta_generic_to_shared(smem_dst);
    asm volatile("cp.async.cg.shared.global [%0], [%1], 16;\n" :: "r"(a), "l"(gsrc));
}

__device__ __forceinline__ float blockReduceSum(float val, float* sh) {
    #pragma unroll
    for (int off = 16; off > 0; off >>= 1)
        val += __shfl_xor_sync(0xffffffffu, val, off);
    int w = threadIdx.x >> 5, l = threadIdx.x & 31;
    __syncthreads();
    if (l == 0) sh[w] = val;
    __syncthreads();
    float r = (threadIdx.x < (blockDim.x >> 5)) ? sh[threadIdx.x] : 0.0f;
    if (w == 0) {
        #pragma unroll
        for (int off = 16; off > 0; off >>= 1)
            r += __shfl_xor_sync(0xffffffffu, r, off);
        if (l == 0) sh[0] = r;
    }
    __syncthreads();
    return sh[0];
}

// ------------------------------------------------------------------
// tf32 pre-rounding of a buffer (vectorized)
// ------------------------------------------------------------------
__global__ void round_kernel(const uint4* __restrict__ src, uint4* __restrict__ dst, int n4) {
    int i = blockIdx.x * blockDim.x + threadIdx.x;
    if (i < n4) {
        uint4 u = src[i];
        u.x = rtf(u.x); u.y = rtf(u.y); u.z = rtf(u.z); u.w = rtf(u.w);
        dst[i] = u;
    }
}

// ------------------------------------------------------------------
// sin/cos rotary tables (double precision)
// ------------------------------------------------------------------
__global__ void sincos_kernel(float* __restrict__ sint, float* __restrict__ cost) {
    int idx = blockIdx.x * blockDim.x + threadIdx.x;
    if (idx >= SS * 32) return;
    int i = idx & 31;
    int s = idx >> 5;
    double ang = pow(10000.0, -(double)i / 31.0);
    double a = (double)s * ang;
    sint[idx] = (float)sin(a);
    cost[idx] = (float)cos(a);
}

// ------------------------------------------------------------------
// Embedding with right-shift
// ------------------------------------------------------------------
__global__ void embed_kernel(const int* __restrict__ tokens,
                             const float* __restrict__ emb,
                             float* __restrict__ h) {
    int idx = blockIdx.x * blockDim.x + threadIdx.x;
    if (idx >= MM * DD) return;
    int d  = idx & (DD - 1);
    int bs = idx / DD;
    int s  = bs & (SS - 1);
    int b  = bs / SS;
    int tok = (s == 0) ? 0 : tokens[b * SS + s - 1];
    h[idx] = emb[tok * DD + d] * 32.0f;
}

// ------------------------------------------------------------------
// LayerNorm (two-pass, eps 1e-5). Output tf32-rounded (GEMM A input).
// ------------------------------------------------------------------
__global__ __launch_bounds__(256)
void ln_kernel(const float* __restrict__ x, const float* __restrict__ sc,
               const float* __restrict__ bi, float* __restrict__ y) {
    __shared__ float sh[32];
    int row = blockIdx.x;
    int tid = threadIdx.x;
    const float* xr = x + (size_t)row * DD;
    float v[4];
    float sum = 0.0f;
    #pragma unroll
    for (int j = 0; j < 4; j++) { v[j] = xr[tid + j * 256]; sum += v[j]; }
    sum = blockReduceSum(sum, sh);
    float mean = sum * (1.0f / 1024.0f);
    float vs = 0.0f;
    #pragma unroll
    for (int j = 0; j < 4; j++) { float d = v[j] - mean; vs += d * d; }
    vs = blockReduceSum(vs, sh);
    float invstd = rsqrtf(vs * (1.0f / 1024.0f) + 1e-5f);
    float* yr = y + (size_t)row * DD;
    #pragma unroll
    for (int j = 0; j < 4; j++) {
        int c = tid + j * 256;
        yr[c] = rtf_f((v[j] - mean) * invstd * sc[c] + bi[c]);
    }
}

// ------------------------------------------------------------------
// TF32 tensor-core GEMM: C[M,N] = A[M,K] @ B[K,N]
// A and B must be tf32-pre-rounded fp32 (HW truncation is then lossless).
// Block tile 128x128, BK=32, 256 threads, warp tile 32x64.
// cp.async double-buffered. No cvt in the mainloop.
// epi bitmask: 1 = +bias, 2 = gelu (output tf32-rounded), 4 = C += result
// ------------------------------------------------------------------
#define ASZ (128 * 36)     // A smem stage, stride 36 words (conflict-free)
#define BSZ (32 * 136)     // B smem stage, stride 136 words (conflict-free)
#define STAGES 2
#define GEMM_SMEM (STAGES * (ASZ + BSZ) * 4)

__device__ __forceinline__ void mma_tf32(float* c, const uint32_t* a, const uint32_t* b) {
    asm volatile(
        "mma.sync.aligned.m16n8k8.row.col.f32.tf32.tf32.f32 "
        "{%0,%1,%2,%3}, {%4,%5,%6,%7}, {%8,%9}, {%0,%1,%2,%3};\n"
        : "+f"(c[0]), "+f"(c[1]), "+f"(c[2]), "+f"(c[3])
        : "r"(a[0]), "r"(a[1]), "r"(a[2]), "r"(a[3]), "r"(b[0]), "r"(b[1]));
}

__global__ __launch_bounds__(256, 2)
void gemm_tf32_kernel(const float* __restrict__ A, const float* __restrict__ B,
                      const float* __restrict__ bias, float* __restrict__ C,
                      int M, int N, int K, int epi) {
    extern __shared__ uint32_t smu[];
    uint32_t* As = smu;                     // [STAGES][ASZ]
    uint32_t* Bs = smu + STAGES * ASZ;      // [STAGES][BSZ]

    int tid  = threadIdx.x;
    int wid  = tid >> 5, lane = tid & 31;
    int g    = lane >> 2, t = lane & 3;
    int wm   = wid & 3;              // warp row (0..3) -> m offset wm*32
    int wn   = wid >> 2;             // warp col (0..1) -> n offset wn*64
    int m0   = blockIdx.y * 128, n0 = blockIdx.x * 128;

    float acc[2][8][4];
    #pragma unroll
    for (int i = 0; i < 2; i++)
        #pragma unroll
        for (int j = 0; j < 8; j++)
            #pragma unroll
            for (int r = 0; r < 4; r++) acc[i][j][r] = 0.0f;

    int nk = K >> 5;   // K/32 tiles

    // Pre-computed loader indices
    int a_r = tid >> 3, a_c4 = (tid & 7) * 4;     // + q*32 rows
    int b_r = tid >> 5, b_c4 = (tid & 31) * 4;    // + q*8 rows

    #define ISSUE_STAGE(kt)                                                      \
    do {                                                                         \
        int _kb = (kt) << 5;                                                     \
        uint32_t* _Aw = As + ((kt) & 1) * ASZ;                                   \
        uint32_t* _Bw = Bs + ((kt) & 1) * BSZ;                                   \
        _Pragma("unroll")                                                        \
        for (int q = 0; q < 4; q++) {                                            \
            int r = a_r + q * 32;                                                \
            cp16(&_Aw[r * 36 + a_c4], &A[(size_t)(m0 + r) * K + _kb + a_c4]);    \
        }                                                                        \
        _Pragma("unroll")                                                        \
        for (int q = 0; q < 4; q++) {                                            \
            int r = b_r + q * 8;                                                 \
            cp16(&_Bw[r * 136 + b_c4], &B[(size_t)(_kb + r) * N + n0 + b_c4]);   \
        }                                                                        \
        asm volatile("cp.async.commit_group;\n");                                \
    } while (0)

    ISSUE_STAGE(0);
    ISSUE_STAGE(1);

    for (int kt = 0; kt < nk; kt++) {
        asm volatile("cp.async.wait_group 1;\n");
        __syncthreads();

        const uint32_t* Ab = As + (kt & 1) * ASZ;
        const uint32_t* Bb = Bs + (kt & 1) * BSZ;

        #pragma unroll
        for (int ks = 0; ks < 4; ks++) {
            int kk = ks * 8;
            uint32_t a[2][4], b[8][2];
            #pragma unroll
            for (int i = 0; i < 2; i++) {
                int rb = wm * 32 + i * 16 + g;
                a[i][0] = Ab[rb * 36 + kk + t];
                a[i][1] = Ab[(rb + 8) * 36 + kk + t];
                a[i][2] = Ab[rb * 36 + kk + t + 4];
                a[i][3] = Ab[(rb + 8) * 36 + kk + t + 4];
            }
            #pragma unroll
            for (int j = 0; j < 8; j++) {
                int cb = wn * 64 + j * 8 + g;
                b[j][0] = Bb[(kk + t) * 136 + cb];
                b[j][1] = Bb[(kk + t + 4) * 136 + cb];
            }
            #pragma unroll
            for (int i = 0; i < 2; i++)
                #pragma unroll
                for (int j = 0; j < 8; j++)
                    mma_tf32(acc[i][j], a[i], b[j]);
        }

        __syncthreads();   // all warps done reading this buffer
        if (kt + 2 < nk) ISSUE_STAGE(kt + 2);
    }

    // ---- epilogue
    bool do_bias = (epi & 1), do_gelu = (epi & 2), do_acc = (epi & 4);
    #pragma unroll
    for (int i = 0; i < 2; i++) {
        int row0 = m0 + wm * 32 + i * 16 + g;
        #pragma unroll
        for (int j = 0; j < 8; j++) {
            int col = n0 + wn * 64 + j * 8 + 2 * t;
            float b0v = 0.0f, b1v = 0.0f;
            if (do_bias) { b0v = bias[col]; b1v = bias[col + 1]; }
            float v00 = acc[i][j][0] + b0v, v01 = acc[i][j][1] + b1v;
            float v10 = acc[i][j][2] + b0v, v11 = acc[i][j][3] + b1v;
            if (do_gelu) {
                v00 = rtf_f(gelu_tanh(v00)); v01 = rtf_f(gelu_tanh(v01));
                v10 = rtf_f(gelu_tanh(v10)); v11 = rtf_f(gelu_tanh(v11));
            }
            float* p0 = &C[(size_t)row0 * N + col];
            float* p1 = &C[(size_t)(row0 + 8) * N + col];
            if (do_acc) {
                float2 o0 = *(float2*)p0;
                float2 o1 = *(float2*)p1;
                v00 += o0.x; v01 += o0.y;
                v10 += o1.x; v11 += o1.y;
            }
            *(float2*)p0 = make_float2(v00, v01);
            *(float2*)p1 = make_float2(v10, v11);
        }
    }
}

// ------------------------------------------------------------------
// Rotary (interleaved pairs), k also scaled by DK^-0.5 = 0.125
// ------------------------------------------------------------------
__global__ void rotary_kernel(float* __restrict__ q, float* __restrict__ k,
                              const float* __restrict__ sint,
                              const float* __restrict__ cost) {
    int idx = blockIdx.x * blockDim.x + threadIdx.x;
    if (idx >= BB * SS * HH * 32) return;
    int i  = idx & 31;
    int t  = idx >> 5;
    int h  = t & 15;
    int bs = t >> 4;
    int s  = bs & (SS - 1);
    float sn = sint[s * 32 + i];
    float cs = cost[s * 32 + i];
    size_t base = (size_t)bs * DD + h * 64 + 2 * i;
    float q0 = q[base], q1 = q[base + 1];
    q[base]     = q0 * cs - q1 * sn;
    q[base + 1] = q1 * cs + q0 * sn;
    float k0 = k[base], k1 = k[base + 1];
    k[base]     = (k0 * cs - k1 * sn) * 0.125f;
    k[base + 1] = (k1 * cs + k0 * sn) * 0.125f;
}

// ------------------------------------------------------------------
// Fused retention attention. Output tf32-rounded (Wo GEMM A input).
// ------------------------------------------------------------------
#define ATTN_SHMEM ((64*68*2 + 64*128 + 64*65 + 64 + 64 + 256) * 4)

__global__ __launch_bounds__(256)
void attn_kernel(const float* __restrict__ q, const float* __restrict__ k,
                 const float* __restrict__ v, const float* __restrict__ g,
                 float* __restrict__ outp) {
    extern __shared__ float sh[];
    float* QsT   = sh;
    float* KsT   = QsT + 64 * 68;
    float* Vs    = KsT + 64 * 68;
    float* St    = Vs + 64 * 128;
    float* absum = St + 64 * 65;
    float* crow  = absum + 64;
    float* red   = crow + 64;

    int tid = threadIdx.x;
    int nt = blockIdx.x, h = blockIdx.y, b = blockIdx.z;
    int n0 = nt * 64;
    int tx = tid & 15, ty = tid >> 4;

    double gamma_d = 1.0 - exp2((double)(-5 - h));
    float lg2g = (float)log2(gamma_d);

    #pragma unroll
    for (int qq = 0; qq < 4; qq++) {
        int p = tid + qq * 256;
        int r = p >> 4;
        int kq = (p & 15) * 4;
        float4 t4 = *(const float4*)&q[((size_t)(b * SS + n0 + r)) * DD + h * 64 + kq];
        QsT[(kq + 0) * 68 + r] = t4.x;
        QsT[(kq + 1) * 68 + r] = t4.y;
        QsT[(kq + 2) * 68 + r] = t4.z;
        QsT[(kq + 3) * 68 + r] = t4.w;
    }
    if (tid < 64) {
        absum[tid] = 0.0f;
        int n = n0 + tid;
        double ssum = (1.0 - pow(gamma_d, (double)(n + 1))) / (1.0 - gamma_d);
        crow[tid] = (float)(1.0 / sqrt(ssum));
    }
    float oa[32];
    #pragma unroll
    for (int i = 0; i < 32; i++) oa[i] = 0.0f;
    int ro = tid >> 2, cg = tid & 3;

    for (int mt = 0; mt <= nt; mt++) {
        int m0 = mt * 64;
        __syncthreads();
        #pragma unroll
        for (int qq = 0; qq < 4; qq++) {
            int p = tid + qq * 256;
            int m = p >> 4;
            int kq = (p & 15) * 4;
            float4 t4 = *(const float4*)&k[((size_t)(b * SS + m0 + m)) * DD + h * 64 + kq];
            KsT[(kq + 0) * 68 + m] = t4.x;
            KsT[(kq + 1) * 68 + m] = t4.y;
            KsT[(kq + 2) * 68 + m] = t4.z;
            KsT[(kq + 3) * 68 + m] = t4.w;
        }
        #pragma unroll
        for (int qq = 0; qq < 8; qq++) {
            int p = tid + qq * 256;
            int m = p >> 5;
            int c4 = (p & 31) * 4;
            *(float4*)&Vs[m * 128 + c4] =
                *(const float4*)&v[((size_t)(b * SS + m0 + m)) * (2 * DD) + h * 128 + c4];
        }
        __syncthreads();

        float scv[4][4] = {};
        #pragma unroll 4
        for (int kk = 0; kk < 64; kk++) {
            float4 av = *(const float4*)&QsT[kk * 68 + ty * 4];
            float4 bv = *(const float4*)&KsT[kk * 68 + tx * 4];
            float a[4] = {av.x, av.y, av.z, av.w};
            float bb[4] = {bv.x, bv.y, bv.z, bv.w};
            #pragma unroll
            for (int i = 0; i < 4; i++)
                #pragma unroll
                for (int j = 0; j < 4; j++)
                    scv[i][j] += a[i] * bb[j];
        }
        float aps[4];
        #pragma unroll
        for (int i = 0; i < 4; i++) {
            int r = ty * 4 + i;
            int n = n0 + r;
            float cc = crow[r];
            float part = 0.0f;
            #pragma unroll
            for (int j = 0; j < 4; j++) {
                int m = m0 + tx * 4 + j;
                float t = 0.0f;
                if (m <= n) t = scv[i][j] * exp2f((float)(n - m) * lg2g) * cc;
                St[r * 65 + tx * 4 + j] = t;
                part += fabsf(t);
            }
            aps[i] = part;
        }
        #pragma unroll
        for (int i = 0; i < 4; i++) {
            float p4 = aps[i];
            #pragma unroll
            for (int off = 8; off > 0; off >>= 1)
                p4 += __shfl_xor_sync(0xffffffffu, p4, off);
            if (tx == 0) absum[ty * 4 + i] += p4;
        }
        __syncthreads();

        for (int m = 0; m < 64; m++) {
            float sv = St[ro * 65 + m];
            const float* vr = &Vs[m * 128];
            #pragma unroll
            for (int jj = 0; jj < 8; jj++) {
                float4 vv = *(const float4*)&vr[jj * 16 + cg * 4];
                oa[jj * 4 + 0] += sv * vv.x;
                oa[jj * 4 + 1] += sv * vv.y;
                oa[jj * 4 + 2] += sv * vv.z;
                oa[jj * 4 + 3] += sv * vv.w;
            }
        }
    }
    __syncthreads();

    float inv = 1.0f / fmaxf(1.0f, absum[ro]);
    float ssq = 0.0f;
    #pragma unroll
    for (int t = 0; t < 32; t++) { oa[t] *= inv; ssq += oa[t] * oa[t]; }
    red[ro * 4 + cg] = ssq;
    __syncthreads();
    float sum = red[ro * 4 + 0] + red[ro * 4 + 1] + red[ro * 4 + 2] + red[ro * 4 + 3];
    float scale = rsqrtf(sum * (1.0f / 128.0f) + 1e-6f);
    int n = n0 + ro;
    size_t gb = ((size_t)(b * SS + n)) * (2 * DD) + h * 128;
    #pragma unroll
    for (int jj = 0; jj < 8; jj++)
        #pragma unroll
        for (int qi = 0; qi < 4; qi++) {
            int c = jj * 16 + cg * 4 + qi;
            float gv = g[gb + c];
            float sl = gv / (1.0f + expf(-gv));
            outp[gb + c] = rtf_f(sl * (oa[jj * 4 + qi] * scale));
        }
}

// ------------------------------------------------------------------
// Final logits + log_softmax (V=2), one warp per token
// ------------------------------------------------------------------
__global__ void logits_kernel(const float* __restrict__ x,
                              const float* __restrict__ Wout,
                              float* __restrict__ outp) {
    int gt = blockIdx.x * blockDim.x + threadIdx.x;
    int warp = gt >> 5, lane = gt & 31;
    if (warp >= MM) return;
    const float* xr = x + (size_t)warp * DD;
    float a0 = 0.0f, a1 = 0.0f;
    for (int kk = lane; kk < DD; kk += 32) {
        float xv = xr[kk];
        a0 += xv * Wout[kk * 2 + 0];
        a1 += xv * Wout[kk * 2 + 1];
    }
    #pragma unroll
    for (int off = 16; off > 0; off >>= 1) {
        a0 += __shfl_xor_sync(0xffffffffu, a0, off);
        a1 += __shfl_xor_sync(0xffffffffu, a1, off);
    }
    if (lane == 0) {
        float mx = fmaxf(a0, a1);
        float lse = mx + logf(expf(a0 - mx) + expf(a1 - mx));
        outp[warp * 2 + 0] = a0 - lse;
        outp[warp * 2 + 1] = a1 - lse;
    }
}

// ------------------------------------------------------------------
// Orchestration
// ------------------------------------------------------------------
extern "C" void kernel_launch(void* const* d_in, const int* in_sizes, int n_in,
                              void* d_out, int out_size) {
    const int*   tokens = (const int*)  d_in[0];
    const float* emb    = (const float*)d_in[1];
    const float* Wq     = (const float*)d_in[2];
    const float* Wk     = (const float*)d_in[3];
    const float* Wv     = (const float*)d_in[4];
    const float* Wg     = (const float*)d_in[5];
    const float* Wo     = (const float*)d_in[6];
    const float* ln1_s  = (const float*)d_in[7];
    const float* ln1_b  = (const float*)d_in[8];
    const float* ln2_s  = (const float*)d_in[9];
    const float* ln2_b  = (const float*)d_in[10];
    const float* W1     = (const float*)d_in[11];
    const float* b1     = (const float*)d_in[12];
    const float* W2     = (const float*)d_in[13];
    const float* b2     = (const float*)d_in[14];
    const float* lnf_s  = (const float*)d_in[15];
    const float* lnf_b  = (const float*)d_in[16];
    const float* Wout   = (const float*)d_in[17];

    float *h, *x, *q, *k, *v, *g, *ao, *ffn, *sint, *cost;
    float *wq, *wk, *wv, *wg, *wo, *w1, *w2;
    cudaGetSymbolAddress((void**)&h,    g_h);
    cudaGetSymbolAddress((void**)&x,    g_x);
    cudaGetSymbolAddress((void**)&q,    g_q);
    cudaGetSymbolAddress((void**)&k,    g_k);
    cudaGetSymbolAddress((void**)&v,    g_v);
    cudaGetSymbolAddress((void**)&g,    g_g);
    cudaGetSymbolAddress((void**)&ao,   g_ao);
    cudaGetSymbolAddress((void**)&ffn,  g_ffn);
    cudaGetSymbolAddress((void**)&sint, g_sin);
    cudaGetSymbolAddress((void**)&cost, g_cos);
    cudaGetSymbolAddress((void**)&wq,   g_wq);
    cudaGetSymbolAddress((void**)&wk,   g_wk);
    cudaGetSymbolAddress((void**)&wv,   g_wv);
    cudaGetSymbolAddress((void**)&wg,   g_wg);
    cudaGetSymbolAddress((void**)&wo,   g_wo);
    cudaGetSymbolAddress((void**)&w1,   g_w1);
    cudaGetSymbolAddress((void**)&w2,   g_w2);

    cudaFuncSetAttribute(attn_kernel, cudaFuncAttributeMaxDynamicSharedMemorySize,
                         ATTN_SHMEM);
    cudaFuncSetAttribute(gemm_tf32_kernel, cudaFuncAttributeMaxDynamicSharedMemorySize,
                         GEMM_SMEM);

    sincos_kernel<<<(SS * 32 + 255) / 256, 256>>>(sint, cost);
    embed_kernel<<<(MM * DD + 255) / 256, 256>>>(tokens, emb, h);

    // Pre-round all weights to tf32 values (once per launch)
    #define ROUND(src, dst, n)                                                   \
        round_kernel<<<((n) / 4 + 255) / 256, 256>>>(                            \
            (const uint4*)(src), (uint4*)(dst), (n) / 4)
    ROUND(Wq, wq, LL * DD * DD);
    ROUND(Wk, wk, LL * DD * DD);
    ROUND(Wv, wv, LL * DD * 2 * DD);
    ROUND(Wg, wg, LL * DD * 2 * DD);
    ROUND(Wo, wo, LL * 2 * DD * DD);
    ROUND(W1, w1, LL * DD * FFN_);
    ROUND(W2, w2, LL * FFN_ * DD);

    for (int l = 0; l < LL; l++) {
        const float* Wq_l = wq + (size_t)l * DD * DD;
        const float* Wk_l = wk + (size_t)l * DD * DD;
        const float* Wv_l = wv + (size_t)l * DD * 2 * DD;
        const float* Wg_l = wg + (size_t)l * DD * 2 * DD;
        const float* Wo_l = wo + (size_t)l * 2 * DD * DD;
        const float* W1_l = w1 + (size_t)l * DD * FFN_;
        const float* W2_l = w2 + (size_t)l * FFN_ * DD;
        const float* b1_l = b1 + (size_t)l * FFN_;
        const float* b2_l = b2 + (size_t)l * DD;

        // --- MSR block ---
        ln_kernel<<<MM, 256>>>(h, ln1_s + l * DD, ln1_b + l * DD, x);
        gemm_tf32_kernel<<<dim3(DD / 128, MM / 128), 256, GEMM_SMEM>>>(
            x, Wq_l, nullptr, q, MM, DD, DD, 0);
        gemm_tf32_kernel<<<dim3(DD / 128, MM / 128), 256, GEMM_SMEM>>>(
            x, Wk_l, nullptr, k, MM, DD, DD, 0);
        gemm_tf32_kernel<<<dim3(2 * DD / 128, MM / 128), 256, GEMM_SMEM>>>(
            x, Wv_l, nullptr, v, MM, 2 * DD, DD, 0);
        gemm_tf32_kernel<<<dim3(2 * DD / 128, MM / 128), 256, GEMM_SMEM>>>(
            x, Wg_l, nullptr, g, MM, 2 * DD, DD, 0);
        rotary_kernel<<<(BB * SS * HH * 32 + 255) / 256, 256>>>(q, k, sint, cost);
        attn_kernel<<<dim3(SS / 64, HH, BB), 256, ATTN_SHMEM>>>(q, k, v, g, ao);
        // h += ao @ Wo   (residual fused into epilogue, epi=4)
        gemm_tf32_kernel<<<dim3(DD / 128, MM / 128), 256, GEMM_SMEM>>>(
            ao, Wo_l, nullptr, h, MM, DD, 2 * DD, 4);

        // --- FFN block ---
        ln_kernel<<<MM, 256>>>(h, ln2_s + l * DD, ln2_b + l * DD, x);
        gemm_tf32_kernel<<<dim3(FFN_ / 128, MM / 128), 256, GEMM_SMEM>>>(
            x, W1_l, b1_l, ffn, MM, FFN_, DD, 3);        // bias + gelu (rounded)
        // h += gelu(...) @ W2 + b2   (bias + residual, epi=5)
        gemm_tf32_kernel<<<dim3(DD / 128, MM / 128), 256, GEMM_SMEM>>>(
            ffn, W2_l, b2_l, h, MM, DD, FFN_, 5);
    }

    ln_kernel<<<MM, 256>>>(h, lnf_s, lnf_b, x);
    logits_kernel<<<MM * 32 / 256, 256>>>(x, Wout, (float*)d_out);
}

// round 13
// speedup vs baseline: 1.0235x; 1.0235x over previous
#include <cuda_runtime.h>
#include <math.h>
#include <stdint.h>

#define BB   4
#define SS   1024
#define DD   1024
#define HH   16
#define DK_  64
#define DV_  128
#define LL   3
#define FFN_ 4096
#define MM   (BB*SS)   // 4096 tokens
#define NQKVG (6*DD)   // 6144 fused projection width

// ------------------------------------------------------------------
// Scratch buffers (static device allocations; no cudaMalloc allowed)
// ------------------------------------------------------------------
__device__ float g_h   [MM*DD];        // residual stream
__device__ float g_x   [MM*DD];        // LN output (tf32-rounded)
__device__ float g_qkvg[MM*NQKVG];     // fused q|k|v|g projections
__device__ float g_ao  [MM*2*DD];      // gated attention output (tf32-rounded)
__device__ float g_ffn [MM*FFN_];      // FFN intermediate (tf32-rounded)
__device__ float g_sin [SS*32];
__device__ float g_cos [SS*32];
// tf32-rounded weight copies
__device__ float g_wqkvg[LL*DD*NQKVG]; // concat(Wq|Wk|Wv|Wg), rounded
__device__ float g_wo[LL*2*DD*DD];
__device__ float g_w1[LL*DD*FFN_];
__device__ float g_w2[LL*FFN_*DD];

// ------------------------------------------------------------------
// Helpers
// ------------------------------------------------------------------
__device__ __forceinline__ float gelu_tanh(float v) {
    const float c = 0.7978845608028654f;   // sqrt(2/pi)
    return 0.5f * v * (1.0f + tanhf(c * (v + 0.044715f * v * v * v)));
}

// round-to-nearest tf32 on a raw fp32 bit pattern (low 13 bits -> 0)
__device__ __forceinline__ uint32_t rtf(uint32_t bits) {
    uint32_t r;
    asm("cvt.rna.tf32.f32 %0, %1;" : "=r"(r) : "r"(bits));
    return r;
}
__device__ __forceinline__ float rtf_f(float x) {
    return __uint_as_float(rtf(__float_as_uint(x)));
}

__device__ __forceinline__ void cp16(void* smem_dst, const void* gsrc) {
    uint32_t a = (uint32_t)__cvta_generic_to_shared(smem_dst);
    asm volatile("cp.async.cg.shared.global [%0], [%1], 16;\n" :: "r"(a), "l"(gsrc));
}

__device__ __forceinline__ float blockReduceSum(float val, float* sh) {
    #pragma unroll
    for (int off = 16; off > 0; off >>= 1)
        val += __shfl_xor_sync(0xffffffffu, val, off);
    int w = threadIdx.x >> 5, l = threadIdx.x & 31;
    __syncthreads();
    if (l == 0) sh[w] = val;
    __syncthreads();
    float r = (threadIdx.x < (blockDim.x >> 5)) ? sh[threadIdx.x] : 0.0f;
    if (w == 0) {
        #pragma unroll
        for (int off = 16; off > 0; off >>= 1)
            r += __shfl_xor_sync(0xffffffffu, r, off);
        if (l == 0) sh[0] = r;
    }
    __syncthreads();
    return sh[0];
}

// ------------------------------------------------------------------
// tf32 pre-rounding of a buffer (vectorized)
// ------------------------------------------------------------------
__global__ void round_kernel(const uint4* __restrict__ src, uint4* __restrict__ dst, int n4) {
    int i = blockIdx.x * blockDim.x + threadIdx.x;
    if (i < n4) {
        uint4 u = src[i];
        u.x = rtf(u.x); u.y = rtf(u.y); u.z = rtf(u.z); u.w = rtf(u.w);
        dst[i] = u;
    }
}

// ------------------------------------------------------------------
// Concat Wq|Wk|Wv|Wg per layer into [D, 6144] with tf32 rounding
// ------------------------------------------------------------------
__global__ void concat_round_kernel(const uint4* __restrict__ Wq,
                                    const uint4* __restrict__ Wk,
                                    const uint4* __restrict__ Wv,
                                    const uint4* __restrict__ Wg,
                                    uint4* __restrict__ dst, int n4) {
    int i = blockIdx.x * blockDim.x + threadIdx.x;   // n4 = LL*DD*6144/4
    if (i >= n4) return;
    int o    = i * 4;
    int l    = o / (DD * NQKVG);
    int rem  = o - l * (DD * NQKVG);
    int kk   = rem / NQKVG;
    int j    = rem - kk * NQKVG;
    uint4 u;
    int seg = j >> 10;     // 1024-wide segments
    if (seg == 0)       u = Wq[((size_t)l * DD * DD   + (size_t)kk * DD   + j)          >> 2];
    else if (seg == 1)  u = Wk[((size_t)l * DD * DD   + (size_t)kk * DD   + (j - DD))   >> 2];
    else if (seg <= 3)  u = Wv[((size_t)l * DD * 2*DD + (size_t)kk * 2*DD + (j - 2*DD)) >> 2];
    else                u = Wg[((size_t)l * DD * 2*DD + (size_t)kk * 2*DD + (j - 4*DD)) >> 2];
    u.x = rtf(u.x); u.y = rtf(u.y); u.z = rtf(u.z); u.w = rtf(u.w);
    dst[i] = u;
}

// ------------------------------------------------------------------
// sin/cos rotary tables (double precision)
// ------------------------------------------------------------------
__global__ void sincos_kernel(float* __restrict__ sint, float* __restrict__ cost) {
    int idx = blockIdx.x * blockDim.x + threadIdx.x;
    if (idx >= SS * 32) return;
    int i = idx & 31;
    int s = idx >> 5;
    double ang = pow(10000.0, -(double)i / 31.0);
    double a = (double)s * ang;
    sint[idx] = (float)sin(a);
    cost[idx] = (float)cos(a);
}

// ------------------------------------------------------------------
// Embedding with right-shift
// ------------------------------------------------------------------
__global__ void embed_kernel(const int* __restrict__ tokens,
                             const float* __restrict__ emb,
                             float* __restrict__ h) {
    int idx = blockIdx.x * blockDim.x + threadIdx.x;
    if (idx >= MM * DD) return;
    int d  = idx & (DD - 1);
    int bs = idx / DD;
    int s  = bs & (SS - 1);
    int b  = bs / SS;
    int tok = (s == 0) ? 0 : tokens[b * SS + s - 1];
    h[idx] = emb[tok * DD + d] * 32.0f;
}

// ------------------------------------------------------------------
// LayerNorm (two-pass, eps 1e-5). Output tf32-rounded (GEMM A input).
// ------------------------------------------------------------------
__global__ __launch_bounds__(256)
void ln_kernel(const float* __restrict__ x, const float* __restrict__ sc,
               const float* __restrict__ bi, float* __restrict__ y) {
    __shared__ float sh[32];
    int row = blockIdx.x;
    int tid = threadIdx.x;
    const float* xr = x + (size_t)row * DD;
    float v[4];
    float sum = 0.0f;
    #pragma unroll
    for (int j = 0; j < 4; j++) { v[j] = xr[tid + j * 256]; sum += v[j]; }
    sum = blockReduceSum(sum, sh);
    float mean = sum * (1.0f / 1024.0f);
    float vs = 0.0f;
    #pragma unroll
    for (int j = 0; j < 4; j++) { float d = v[j] - mean; vs += d * d; }
    vs = blockReduceSum(vs, sh);
    float invstd = rsqrtf(vs * (1.0f / 1024.0f) + 1e-5f);
    float* yr = y + (size_t)row * DD;
    #pragma unroll
    for (int j = 0; j < 4; j++) {
        int c = tid + j * 256;
        yr[c] = rtf_f((v[j] - mean) * invstd * sc[c] + bi[c]);
    }
}

// ------------------------------------------------------------------
// TF32 tensor-core GEMM: C[M,N] = A[M,K] @ B[K,N]
// A and B tf32-pre-rounded fp32 (HW truncation lossless).
// Block tile 128x128, BK=32, 256 threads, warp tile 32x64.
// 3-stage cp.async pipeline, ONE sync per K-tile, 2 CTAs/SM.
// epi bitmask: 1 = +bias, 2 = gelu (output tf32-rounded), 4 = C += result
// ------------------------------------------------------------------
#define ASZ (128 * 36)     // A smem stage, stride 36 words (conflict-free)
#define BSZ (32 * 136)     // B smem stage, stride 136 words (conflict-free)
#define STAGES 3
#define GEMM_SMEM (STAGES * (ASZ + BSZ) * 4)   // 107,520 B -> 2 CTAs/SM

__device__ __forceinline__ void mma_tf32(float* c, const uint32_t* a, const uint32_t* b) {
    asm volatile(
        "mma.sync.aligned.m16n8k8.row.col.f32.tf32.tf32.f32 "
        "{%0,%1,%2,%3}, {%4,%5,%6,%7}, {%8,%9}, {%0,%1,%2,%3};\n"
        : "+f"(c[0]), "+f"(c[1]), "+f"(c[2]), "+f"(c[3])
        : "r"(a[0]), "r"(a[1]), "r"(a[2]), "r"(a[3]), "r"(b[0]), "r"(b[1]));
}

__global__ __launch_bounds__(256, 2)
void gemm_tf32_kernel(const float* __restrict__ A, const float* __restrict__ B,
                      const float* __restrict__ bias, float* __restrict__ C,
                      int M, int N, int K, int epi) {
    extern __shared__ uint32_t smu[];
    uint32_t* As = smu;                     // [STAGES][ASZ]
    uint32_t* Bs = smu + STAGES * ASZ;      // [STAGES][BSZ]

    int tid  = threadIdx.x;
    int wid  = tid >> 5, lane = tid & 31;
    int g    = lane >> 2, t = lane & 3;
    int wm   = wid & 3;              // warp row (0..3) -> m offset wm*32
    int wn   = wid >> 2;             // warp col (0..1) -> n offset wn*64
    int m0   = blockIdx.y * 128, n0 = blockIdx.x * 128;

    float acc[2][8][4];
    #pragma unroll
    for (int i = 0; i < 2; i++)
        #pragma unroll
        for (int j = 0; j < 8; j++)
            #pragma unroll
            for (int r = 0; r < 4; r++) acc[i][j][r] = 0.0f;

    int nk = K >> 5;   // K/32 tiles

    // Pre-computed loader indices
    int a_r = tid >> 3, a_c4 = (tid & 7) * 4;     // + q*32 rows
    int b_r = tid >> 5, b_c4 = (tid & 31) * 4;    // + q*8 rows

    #define ISSUE_STAGE(kt)                                                      \
    do {                                                                         \
        int _kb = (kt) << 5;                                                     \
        uint32_t* _Aw = As + ((kt) % STAGES) * ASZ;                              \
        uint32_t* _Bw = Bs + ((kt) % STAGES) * BSZ;                              \
        _Pragma("unroll")                                                        \
        for (int q = 0; q < 4; q++) {                                            \
            int r = a_r + q * 32;                                                \
            cp16(&_Aw[r * 36 + a_c4], &A[(size_t)(m0 + r) * K + _kb + a_c4]);    \
        }                                                                        \
        _Pragma("unroll")                                                        \
        for (int q = 0; q < 4; q++) {                                            \
            int r = b_r + q * 8;                                                 \
            cp16(&_Bw[r * 136 + b_c4], &B[(size_t)(_kb + r) * N + n0 + b_c4]);   \
        }                                                                        \
        asm volatile("cp.async.commit_group;\n");                                \
    } while (0)

    ISSUE_STAGE(0);
    ISSUE_STAGE(1);

    for (int kt = 0; kt < nk; kt++) {
        asm volatile("cp.async.wait_group 1;\n");
        __syncthreads();
        if (kt + 2 < nk) ISSUE_STAGE(kt + 2);

        const uint32_t* Ab = As + (kt % STAGES) * ASZ;
        const uint32_t* Bb = Bs + (kt % STAGES) * BSZ;

        #pragma unroll
        for (int ks = 0; ks < 4; ks++) {
            int kk = ks * 8;
            uint32_t a[2][4], b[8][2];
            #pragma unroll
            for (int i = 0; i < 2; i++) {
                int rb = wm * 32 + i * 16 + g;
                a[i][0] = Ab[rb * 36 + kk + t];
                a[i][1] = Ab[(rb + 8) * 36 + kk + t];
                a[i][2] = Ab[rb * 36 + kk + t + 4];
                a[i][3] = Ab[(rb + 8) * 36 + kk + t + 4];
            }
            #pragma unroll
            for (int j = 0; j < 8; j++) {
                int cb = wn * 64 + j * 8 + g;
                b[j][0] = Bb[(kk + t) * 136 + cb];
                b[j][1] = Bb[(kk + t + 4) * 136 + cb];
            }
            #pragma unroll
            for (int i = 0; i < 2; i++)
                #pragma unroll
                for (int j = 0; j < 8; j++)
                    mma_tf32(acc[i][j], a[i], b[j]);
        }
    }

    // ---- epilogue
    bool do_bias = (epi & 1), do_gelu = (epi & 2), do_acc = (epi & 4);
    #pragma unroll
    for (int i = 0; i < 2; i++) {
        int row0 = m0 + wm * 32 + i * 16 + g;
        #pragma unroll
        for (int j = 0; j < 8; j++) {
            int col = n0 + wn * 64 + j * 8 + 2 * t;
            float b0v = 0.0f, b1v = 0.0f;
            if (do_bias) { b0v = bias[col]; b1v = bias[col + 1]; }
            float v00 = acc[i][j][0] + b0v, v01 = acc[i][j][1] + b1v;
            float v10 = acc[i][j][2] + b0v, v11 = acc[i][j][3] + b1v;
            if (do_gelu) {
                v00 = rtf_f(gelu_tanh(v00)); v01 = rtf_f(gelu_tanh(v01));
                v10 = rtf_f(gelu_tanh(v10)); v11 = rtf_f(gelu_tanh(v11));
            }
            float* p0 = &C[(size_t)row0 * N + col];
            float* p1 = &C[(size_t)(row0 + 8) * N + col];
            if (do_acc) {
                float2 o0 = *(float2*)p0;
                float2 o1 = *(float2*)p1;
                v00 += o0.x; v01 += o0.y;
                v10 += o1.x; v11 += o1.y;
            }
            *(float2*)p0 = make_float2(v00, v01);
            *(float2*)p1 = make_float2(v10, v11);
        }
    }
}

// ------------------------------------------------------------------
// Rotary on fused qkvg buffer (q at col 0, k at col DD), row stride 6144
// k also scaled by DK^-0.5 = 0.125
// ------------------------------------------------------------------
__global__ void rotary_kernel(float* __restrict__ qkvg,
                              const float* __restrict__ sint,
                              const float* __restrict__ cost) {
    int idx = blockIdx.x * blockDim.x + threadIdx.x;
    if (idx >= BB * SS * HH * 32) return;
    int i  = idx & 31;
    int t  = idx >> 5;
    int h  = t & 15;
    int bs = t >> 4;
    int s  = bs & (SS - 1);
    float sn = sint[s * 32 + i];
    float cs = cost[s * 32 + i];
    size_t base = (size_t)bs * NQKVG + h * 64 + 2 * i;
    float q0 = qkvg[base], q1 = qkvg[base + 1];
    qkvg[base]     = q0 * cs - q1 * sn;
    qkvg[base + 1] = q1 * cs + q0 * sn;
    size_t kb = base + DD;
    float k0 = qkvg[kb], k1 = qkvg[kb + 1];
    qkvg[kb]     = (k0 * cs - k1 * sn) * 0.125f;
    qkvg[kb + 1] = (k1 * cs + k0 * sn) * 0.125f;
}

// ------------------------------------------------------------------
// Fused retention attention, reading the fused qkvg buffer.
// Output (ao) tf32-rounded, row stride 2*DD.
// ------------------------------------------------------------------
#define ATTN_SHMEM ((64*68*2 + 64*128 + 64*65 + 64 + 64 + 256) * 4)

__global__ __launch_bounds__(256)
void attn_kernel(const float* __restrict__ qkvg, float* __restrict__ outp) {
    extern __shared__ float sh[];
    float* QsT   = sh;
    float* KsT   = QsT + 64 * 68;
    float* Vs    = KsT + 64 * 68;
    float* St    = Vs + 64 * 128;
    float* absum = St + 64 * 65;
    float* crow  = absum + 64;
    float* red   = crow + 64;

    int tid = threadIdx.x;
    int nt = blockIdx.x, h = blockIdx.y, b = blockIdx.z;
    int n0 = nt * 64;
    int tx = tid & 15, ty = tid >> 4;

    double gamma_d = 1.0 - exp2((double)(-5 - h));
    float lg2g = (float)log2(gamma_d);

    #pragma unroll
    for (int qq = 0; qq < 4; qq++) {
        int p = tid + qq * 256;
        int r = p >> 4;
        int kq = (p & 15) * 4;
        float4 t4 = *(const float4*)&qkvg[((size_t)(b * SS + n0 + r)) * NQKVG + h * 64 + kq];
        QsT[(kq + 0) * 68 + r] = t4.x;
        QsT[(kq + 1) * 68 + r] = t4.y;
        QsT[(kq + 2) * 68 + r] = t4.z;
        QsT[(kq + 3) * 68 + r] = t4.w;
    }
    if (tid < 64) {
        absum[tid] = 0.0f;
        int n = n0 + tid;
        double ssum = (1.0 - pow(gamma_d, (double)(n + 1))) / (1.0 - gamma_d);
        crow[tid] = (float)(1.0 / sqrt(ssum));
    }
    float oa[32];
    #pragma unroll
    for (int i = 0; i < 32; i++) oa[i] = 0.0f;
    int ro = tid >> 2, cg = tid & 3;

    for (int mt = 0; mt <= nt; mt++) {
        int m0 = mt * 64;
        __syncthreads();
        #pragma unroll
        for (int qq = 0; qq < 4; qq++) {
            int p = tid + qq * 256;
            int m = p >> 4;
            int kq = (p & 15) * 4;
            float4 t4 = *(const float4*)&qkvg[((size_t)(b * SS + m0 + m)) * NQKVG + DD + h * 64 + kq];
            KsT[(kq + 0) * 68 + m] = t4.x;
            KsT[(kq + 1) * 68 + m] = t4.y;
            KsT[(kq + 2) * 68 + m] = t4.z;
            KsT[(kq + 3) * 68 + m] = t4.w;
        }
        #pragma unroll
        for (int qq = 0; qq < 8; qq++) {
            int p = tid + qq * 256;
            int m = p >> 5;
            int c4 = (p & 31) * 4;
            *(float4*)&Vs[m * 128 + c4] =
                *(const float4*)&qkvg[((size_t)(b * SS + m0 + m)) * NQKVG + 2 * DD + h * 128 + c4];
        }
        __syncthreads();

        float scv[4][4] = {};
        #pragma unroll 4
        for (int kk = 0; kk < 64; kk++) {
            float4 av = *(const float4*)&QsT[kk * 68 + ty * 4];
            float4 bv = *(const float4*)&KsT[kk * 68 + tx * 4];
            float a[4] = {av.x, av.y, av.z, av.w};
            float bb[4] = {bv.x, bv.y, bv.z, bv.w};
            #pragma unroll
            for (int i = 0; i < 4; i++)
                #pragma unroll
                for (int j = 0; j < 4; j++)
                    scv[i][j] += a[i] * bb[j];
        }
        float aps[4];
        #pragma unroll
        for (int i = 0; i < 4; i++) {
            int r = ty * 4 + i;
            int n = n0 + r;
            float cc = crow[r];
            float part = 0.0f;
            #pragma unroll
            for (int j = 0; j < 4; j++) {
                int m = m0 + tx * 4 + j;
                float t = 0.0f;
                if (m <= n) t = scv[i][j] * exp2f((float)(n - m) * lg2g) * cc;
                St[r * 65 + tx * 4 + j] = t;
                part += fabsf(t);
            }
            aps[i] = part;
        }
        #pragma unroll
        for (int i = 0; i < 4; i++) {
            float p4 = aps[i];
            #pragma unroll
            for (int off = 8; off > 0; off >>= 1)
                p4 += __shfl_xor_sync(0xffffffffu, p4, off);
            if (tx == 0) absum[ty * 4 + i] += p4;
        }
        __syncthreads();

        for (int m = 0; m < 64; m++) {
            float sv = St[ro * 65 + m];
            const float* vr = &Vs[m * 128];
            #pragma unroll
            for (int jj = 0; jj < 8; jj++) {
                float4 vv = *(const float4*)&vr[jj * 16 + cg * 4];
                oa[jj * 4 + 0] += sv * vv.x;
                oa[jj * 4 + 1] += sv * vv.y;
                oa[jj * 4 + 2] += sv * vv.z;
                oa[jj * 4 + 3] += sv * vv.w;
            }
        }
    }
    __syncthreads();

    float inv = 1.0f / fmaxf(1.0f, absum[ro]);
    float ssq = 0.0f;
    #pragma unroll
    for (int t = 0; t < 32; t++) { oa[t] *= inv; ssq += oa[t] * oa[t]; }
    red[ro * 4 + cg] = ssq;
    __syncthreads();
    float sum = red[ro * 4 + 0] + red[ro * 4 + 1] + red[ro * 4 + 2] + red[ro * 4 + 3];
    float scale = rsqrtf(sum * (1.0f / 128.0f) + 1e-6f);
    int n = n0 + ro;
    size_t srcb = ((size_t)(b * SS + n)) * NQKVG + 4 * DD + h * 128;   // gate
    size_t dstb = ((size_t)(b * SS + n)) * (2 * DD) + h * 128;
    #pragma unroll
    for (int jj = 0; jj < 8; jj++)
        #pragma unroll
        for (int qi = 0; qi < 4; qi++) {
            int c = jj * 16 + cg * 4 + qi;
            float gv = qkvg[srcb + c];
            float sl = gv / (1.0f + expf(-gv));
            outp[dstb + c] = rtf_f(sl * (oa[jj * 4 + qi] * scale));
        }
}

// ------------------------------------------------------------------
// Final logits + log_softmax (V=2), one warp per token
// ------------------------------------------------------------------
__global__ void logits_kernel(const float* __restrict__ x,
                              const float* __restrict__ Wout,
                              float* __restrict__ outp) {
    int gt = blockIdx.x * blockDim.x + threadIdx.x;
    int warp = gt >> 5, lane = gt & 31;
    if (warp >= MM) return;
    const float* xr = x + (size_t)warp * DD;
    float a0 = 0.0f, a1 = 0.0f;
    for (int kk = lane; kk < DD; kk += 32) {
        float xv = xr[kk];
        a0 += xv * Wout[kk * 2 + 0];
        a1 += xv * Wout[kk * 2 + 1];
    }
    #pragma unroll
    for (int off = 16; off > 0; off >>= 1) {
        a0 += __shfl_xor_sync(0xffffffffu, a0, off);
        a1 += __shfl_xor_sync(0xffffffffu, a1, off);
    }
    if (lane == 0) {
        float mx = fmaxf(a0, a1);
        float lse = mx + logf(expf(a0 - mx) + expf(a1 - mx));
        outp[warp * 2 + 0] = a0 - lse;
        outp[warp * 2 + 1] = a1 - lse;
    }
}

// ------------------------------------------------------------------
// Orchestration
// ------------------------------------------------------------------
extern "C" void kernel_launch(void* const* d_in, const int* in_sizes, int n_in,
                              void* d_out, int out_size) {
    const int*   tokens = (const int*)  d_in[0];
    const float* emb    = (const float*)d_in[1];
    const float* Wq     = (const float*)d_in[2];
    const float* Wk     = (const float*)d_in[3];
    const float* Wv     = (const float*)d_in[4];
    const float* Wg     = (const float*)d_in[5];
    const float* Wo     = (const float*)d_in[6];
    const float* ln1_s  = (const float*)d_in[7];
    const float* ln1_b  = (const float*)d_in[8];
    const float* ln2_s  = (const float*)d_in[9];
    const float* ln2_b  = (const float*)d_in[10];
    const float* W1     = (const float*)d_in[11];
    const float* b1     = (const float*)d_in[12];
    const float* W2     = (const float*)d_in[13];
    const float* b2     = (const float*)d_in[14];
    const float* lnf_s  = (const float*)d_in[15];
    const float* lnf_b  = (const float*)d_in[16];
    const float* Wout   = (const float*)d_in[17];

    float *h, *x, *qkvg, *ao, *ffn, *sint, *cost;
    float *wqkvg, *wo, *w1, *w2;
    cudaGetSymbolAddress((void**)&h,     g_h);
    cudaGetSymbolAddress((void**)&x,     g_x);
    cudaGetSymbolAddress((void**)&qkvg,  g_qkvg);
    cudaGetSymbolAddress((void**)&ao,    g_ao);
    cudaGetSymbolAddress((void**)&ffn,   g_ffn);
    cudaGetSymbolAddress((void**)&sint,  g_sin);
    cudaGetSymbolAddress((void**)&cost,  g_cos);
    cudaGetSymbolAddress((void**)&wqkvg, g_wqkvg);
    cudaGetSymbolAddress((void**)&wo,    g_wo);
    cudaGetSymbolAddress((void**)&w1,    g_w1);
    cudaGetSymbolAddress((void**)&w2,    g_w2);

    cudaFuncSetAttribute(attn_kernel, cudaFuncAttributeMaxDynamicSharedMemorySize,
                         ATTN_SHMEM);
    cudaFuncSetAttribute(gemm_tf32_kernel, cudaFuncAttributeMaxDynamicSharedMemorySize,
                         GEMM_SMEM);

    sincos_kernel<<<(SS * 32 + 255) / 256, 256>>>(sint, cost);
    embed_kernel<<<(MM * DD + 255) / 256, 256>>>(tokens, emb, h);

    // Pre-round weights to tf32 values (once per launch)
    {
        int n4 = LL * DD * NQKVG / 4;
        concat_round_kernel<<<(n4 + 255) / 256, 256>>>(
            (const uint4*)Wq, (const uint4*)Wk, (const uint4*)Wv, (const uint4*)Wg,
            (uint4*)wqkvg, n4);
    }
    #define ROUND(src, dst, n)                                                   \
        round_kernel<<<((n) / 4 + 255) / 256, 256>>>(                            \
            (const uint4*)(src), (uint4*)(dst), (n) / 4)
    ROUND(Wo, wo, LL * 2 * DD * DD);
    ROUND(W1, w1, LL * DD * FFN_);
    ROUND(W2, w2, LL * FFN_ * DD);

    for (int l = 0; l < LL; l++) {
        const float* Wqkvg_l = wqkvg + (size_t)l * DD * NQKVG;
        const float* Wo_l = wo + (size_t)l * 2 * DD * DD;
        const float* W1_l = w1 + (size_t)l * DD * FFN_;
        const float* W2_l = w2 + (size_t)l * FFN_ * DD;
        const float* b1_l = b1 + (size_t)l * FFN_;
        const float* b2_l = b2 + (size_t)l * DD;

        // --- MSR block ---
        ln_kernel<<<MM, 256>>>(h, ln1_s + l * DD, ln1_b + l * DD, x);
        // fused q|k|v|g projection: [MM, 6144]
        gemm_tf32_kernel<<<dim3(NQKVG / 128, MM / 128), 256, GEMM_SMEM>>>(
            x, Wqkvg_l, nullptr, qkvg, MM, NQKVG, DD, 0);
        rotary_kernel<<<(BB * SS * HH * 32 + 255) / 256, 256>>>(qkvg, sint, cost);
        attn_kernel<<<dim3(SS / 64, HH, BB), 256, ATTN_SHMEM>>>(qkvg, ao);
        // h += ao @ Wo   (residual fused into epilogue, epi=4)
        gemm_tf32_kernel<<<dim3(DD / 128, MM / 128), 256, GEMM_SMEM>>>(
            ao, Wo_l, nullptr, h, MM, DD, 2 * DD, 4);

        // --- FFN block ---
        ln_kernel<<<MM, 256>>>(h, ln2_s + l * DD, ln2_b + l * DD, x);
        gemm_tf32_kernel<<<dim3(FFN_ / 128, MM / 128), 256, GEMM_SMEM>>>(
            x, W1_l, b1_l, ffn, MM, FFN_, DD, 3);        // bias + gelu (rounded)
        // h += gelu(...) @ W2 + b2   (bias + residual, epi=5)
        gemm_tf32_kernel<<<dim3(DD / 128, MM / 128), 256, GEMM_SMEM>>>(
            ffn, W2_l, b2_l, h, MM, DD, FFN_, 5);
    }

    ln_kernel<<<MM, 256>>>(h, lnf_s, lnf_b, x);
    logits_kernel<<<MM * 32 / 256, 256>>>(x, Wout, (float*)d_out);
}

// round 17
// speedup vs baseline: 1.5205x; 1.4856x over previous
#include <cuda_runtime.h>
#include <math.h>
#include <stdint.h>

#define BB   4
#define SS   1024
#define DD   1024
#define HH   16
#define DK_  64
#define DV_  128
#define LL   3
#define FFN_ 4096
#define MM   (BB*SS)   // 4096 tokens
#define NQKVG (6*DD)   // 6144 fused projection width

// ------------------------------------------------------------------
// Scratch buffers (static device allocations; no cudaMalloc allowed)
// ------------------------------------------------------------------
__device__ float g_h   [MM*DD];        // residual stream
__device__ float g_x   [MM*DD];        // LN output (tf32-rounded)
__device__ float g_qkvg[MM*NQKVG];     // fused q|k|v|g projections
__device__ float g_ao  [MM*2*DD];      // gated attention output (tf32-rounded)
__device__ float g_ffn [MM*FFN_];      // FFN intermediate (tf32-rounded)
__device__ float g_sin [SS*32];
__device__ float g_cos [SS*32];
// tf32-rounded weight copies
__device__ float g_wqkvg[LL*DD*NQKVG]; // concat(Wq|Wk|Wv|Wg), rounded
__device__ float g_wo[LL*2*DD*DD];
__device__ float g_w1[LL*DD*FFN_];
__device__ float g_w2[LL*FFN_*DD];

// ------------------------------------------------------------------
// Helpers
// ------------------------------------------------------------------
__device__ __forceinline__ float gelu_tanh(float v) {
    const float c = 0.7978845608028654f;   // sqrt(2/pi)
    return 0.5f * v * (1.0f + tanhf(c * (v + 0.044715f * v * v * v)));
}

// round-to-nearest tf32 on a raw fp32 bit pattern (low 13 bits -> 0)
__device__ __forceinline__ uint32_t rtf(uint32_t bits) {
    uint32_t r;
    asm("cvt.rna.tf32.f32 %0, %1;" : "=r"(r) : "r"(bits));
    return r;
}
__device__ __forceinline__ float rtf_f(float x) {
    return __uint_as_float(rtf(__float_as_uint(x)));
}

__device__ __forceinline__ void cp16(void* smem_dst, const void* gsrc) {
    uint32_t a = (uint32_t)__cvta_generic_to_shared(smem_dst);
    asm volatile("cp.async.cg.shared.global [%0], [%1], 16;\n" :: "r"(a), "l"(gsrc));
}

__device__ __forceinline__ float blockReduceSum(float val, float* sh) {
    #pragma unroll
    for (int off = 16; off > 0; off >>= 1)
        val += __shfl_xor_sync(0xffffffffu, val, off);
    int w = threadIdx.x >> 5, l = threadIdx.x & 31;
    __syncthreads();
    if (l == 0) sh[w] = val;
    __syncthreads();
    float r = (threadIdx.x < (blockDim.x >> 5)) ? sh[threadIdx.x] : 0.0f;
    if (w == 0) {
        #pragma unroll
        for (int off = 16; off > 0; off >>= 1)
            r += __shfl_xor_sync(0xffffffffu, r, off);
        if (l == 0) sh[0] = r;
    }
    __syncthreads();
    return sh[0];
}

__device__ __forceinline__ void mma_tf32(float* c, const uint32_t* a, const uint32_t* b) {
    asm volatile(
        "mma.sync.aligned.m16n8k8.row.col.f32.tf32.tf32.f32 "
        "{%0,%1,%2,%3}, {%4,%5,%6,%7}, {%8,%9}, {%0,%1,%2,%3};\n"
        : "+f"(c[0]), "+f"(c[1]), "+f"(c[2]), "+f"(c[3])
        : "r"(a[0]), "r"(a[1]), "r"(a[2]), "r"(a[3]), "r"(b[0]), "r"(b[1]));
}

// ------------------------------------------------------------------
// tf32 pre-rounding: merged three-buffer version (one launch)
// ------------------------------------------------------------------
__global__ void round3_kernel(const uint4* __restrict__ s0, uint4* __restrict__ d0, int n0_,
                              const uint4* __restrict__ s1, uint4* __restrict__ d1, int n1_,
                              const uint4* __restrict__ s2, uint4* __restrict__ d2, int n2_) {
    int i = blockIdx.x * blockDim.x + threadIdx.x;
    const uint4* s; uint4* d; int j;
    if (i < n0_)                { s = s0; d = d0; j = i; }
    else if (i < n0_ + n1_)     { s = s1; d = d1; j = i - n0_; }
    else if (i < n0_ + n1_ + n2_) { s = s2; d = d2; j = i - n0_ - n1_; }
    else return;
    uint4 u = s[j];
    u.x = rtf(u.x); u.y = rtf(u.y); u.z = rtf(u.z); u.w = rtf(u.w);
    d[j] = u;
}

// ------------------------------------------------------------------
// Concat Wq|Wk|Wv|Wg per layer into [D, 6144] with tf32 rounding
// ------------------------------------------------------------------
__global__ void concat_round_kernel(const uint4* __restrict__ Wq,
                                    const uint4* __restrict__ Wk,
                                    const uint4* __restrict__ Wv,
                                    const uint4* __restrict__ Wg,
                                    uint4* __restrict__ dst, int n4) {
    int i = blockIdx.x * blockDim.x + threadIdx.x;   // n4 = LL*DD*6144/4
    if (i >= n4) return;
    int o    = i * 4;
    int l    = o / (DD * NQKVG);
    int rem  = o - l * (DD * NQKVG);
    int kk   = rem / NQKVG;
    int j    = rem - kk * NQKVG;
    uint4 u;
    int seg = j >> 10;     // 1024-wide segments
    if (seg == 0)       u = Wq[((size_t)l * DD * DD   + (size_t)kk * DD   + j)          >> 2];
    else if (seg == 1)  u = Wk[((size_t)l * DD * DD   + (size_t)kk * DD   + (j - DD))   >> 2];
    else if (seg <= 3)  u = Wv[((size_t)l * DD * 2*DD + (size_t)kk * 2*DD + (j - 2*DD)) >> 2];
    else                u = Wg[((size_t)l * DD * 2*DD + (size_t)kk * 2*DD + (j - 4*DD)) >> 2];
    u.x = rtf(u.x); u.y = rtf(u.y); u.z = rtf(u.z); u.w = rtf(u.w);
    dst[i] = u;
}

// ------------------------------------------------------------------
// sin/cos rotary tables (double precision)
// ------------------------------------------------------------------
__global__ void sincos_kernel(float* __restrict__ sint, float* __restrict__ cost) {
    int idx = blockIdx.x * blockDim.x + threadIdx.x;
    if (idx >= SS * 32) return;
    int i = idx & 31;
    int s = idx >> 5;
    double ang = pow(10000.0, -(double)i / 31.0);
    double a = (double)s * ang;
    sint[idx] = (float)sin(a);
    cost[idx] = (float)cos(a);
}

// ------------------------------------------------------------------
// Embedding with right-shift
// ------------------------------------------------------------------
__global__ void embed_kernel(const int* __restrict__ tokens,
                             const float* __restrict__ emb,
                             float* __restrict__ h) {
    int idx = blockIdx.x * blockDim.x + threadIdx.x;
    if (idx >= MM * DD) return;
    int d  = idx & (DD - 1);
    int bs = idx / DD;
    int s  = bs & (SS - 1);
    int b  = bs / SS;
    int tok = (s == 0) ? 0 : tokens[b * SS + s - 1];
    h[idx] = emb[tok * DD + d] * 32.0f;
}

// ------------------------------------------------------------------
// LayerNorm (two-pass, eps 1e-5). Output tf32-rounded (GEMM A input).
// ------------------------------------------------------------------
__global__ __launch_bounds__(256)
void ln_kernel(const float* __restrict__ x, const float* __restrict__ sc,
               const float* __restrict__ bi, float* __restrict__ y) {
    __shared__ float sh[32];
    int row = blockIdx.x;
    int tid = threadIdx.x;
    const float* xr = x + (size_t)row * DD;
    float v[4];
    float sum = 0.0f;
    #pragma unroll
    for (int j = 0; j < 4; j++) { v[j] = xr[tid + j * 256]; sum += v[j]; }
    sum = blockReduceSum(sum, sh);
    float mean = sum * (1.0f / 1024.0f);
    float vs = 0.0f;
    #pragma unroll
    for (int j = 0; j < 4; j++) { float d = v[j] - mean; vs += d * d; }
    vs = blockReduceSum(vs, sh);
    float invstd = rsqrtf(vs * (1.0f / 1024.0f) + 1e-5f);
    float* yr = y + (size_t)row * DD;
    #pragma unroll
    for (int j = 0; j < 4; j++) {
        int c = tid + j * 256;
        yr[c] = rtf_f((v[j] - mean) * invstd * sc[c] + bi[c]);
    }
}

// ------------------------------------------------------------------
// TF32 tensor-core GEMM (unchanged)
// ------------------------------------------------------------------
#define ASZ (128 * 36)
#define BSZ (32 * 136)
#define STAGES 3
#define GEMM_SMEM (STAGES * (ASZ + BSZ) * 4)   // 107,520 B -> 2 CTAs/SM

__global__ __launch_bounds__(256, 2)
void gemm_tf32_kernel(const float* __restrict__ A, const float* __restrict__ B,
                      const float* __restrict__ bias, float* __restrict__ C,
                      int M, int N, int K, int epi) {
    extern __shared__ uint32_t smu[];
    uint32_t* As = smu;
    uint32_t* Bs = smu + STAGES * ASZ;

    int tid  = threadIdx.x;
    int wid  = tid >> 5, lane = tid & 31;
    int g    = lane >> 2, t = lane & 3;
    int wm   = wid & 3;
    int wn   = wid >> 2;
    int m0   = blockIdx.y * 128, n0 = blockIdx.x * 128;

    float acc[2][8][4];
    #pragma unroll
    for (int i = 0; i < 2; i++)
        #pragma unroll
        for (int j = 0; j < 8; j++)
            #pragma unroll
            for (int r = 0; r < 4; r++) acc[i][j][r] = 0.0f;

    int nk = K >> 5;

    int a_r = tid >> 3, a_c4 = (tid & 7) * 4;
    int b_r = tid >> 5, b_c4 = (tid & 31) * 4;

    #define ISSUE_STAGE(kt)                                                      \
    do {                                                                         \
        int _kb = (kt) << 5;                                                     \
        uint32_t* _Aw = As + ((kt) % STAGES) * ASZ;                              \
        uint32_t* _Bw = Bs + ((kt) % STAGES) * BSZ;                              \
        _Pragma("unroll")                                                        \
        for (int q = 0; q < 4; q++) {                                            \
            int r = a_r + q * 32;                                                \
            cp16(&_Aw[r * 36 + a_c4], &A[(size_t)(m0 + r) * K + _kb + a_c4]);    \
        }                                                                        \
        _Pragma("unroll")                                                        \
        for (int q = 0; q < 4; q++) {                                            \
            int r = b_r + q * 8;                                                 \
            cp16(&_Bw[r * 136 + b_c4], &B[(size_t)(_kb + r) * N + n0 + b_c4]);   \
        }                                                                        \
        asm volatile("cp.async.commit_group;\n");                                \
    } while (0)

    ISSUE_STAGE(0);
    ISSUE_STAGE(1);

    for (int kt = 0; kt < nk; kt++) {
        asm volatile("cp.async.wait_group 1;\n");
        __syncthreads();
        if (kt + 2 < nk) ISSUE_STAGE(kt + 2);

        const uint32_t* Ab = As + (kt % STAGES) * ASZ;
        const uint32_t* Bb = Bs + (kt % STAGES) * BSZ;

        #pragma unroll
        for (int ks = 0; ks < 4; ks++) {
            int kk = ks * 8;
            uint32_t a[2][4], b[8][2];
            #pragma unroll
            for (int i = 0; i < 2; i++) {
                int rb = wm * 32 + i * 16 + g;
                a[i][0] = Ab[rb * 36 + kk + t];
                a[i][1] = Ab[(rb + 8) * 36 + kk + t];
                a[i][2] = Ab[rb * 36 + kk + t + 4];
                a[i][3] = Ab[(rb + 8) * 36 + kk + t + 4];
            }
            #pragma unroll
            for (int j = 0; j < 8; j++) {
                int cb = wn * 64 + j * 8 + g;
                b[j][0] = Bb[(kk + t) * 136 + cb];
                b[j][1] = Bb[(kk + t + 4) * 136 + cb];
            }
            #pragma unroll
            for (int i = 0; i < 2; i++)
                #pragma unroll
                for (int j = 0; j < 8; j++)
                    mma_tf32(acc[i][j], a[i], b[j]);
        }
    }

    bool do_bias = (epi & 1), do_gelu = (epi & 2), do_acc = (epi & 4);
    #pragma unroll
    for (int i = 0; i < 2; i++) {
        int row0 = m0 + wm * 32 + i * 16 + g;
        #pragma unroll
        for (int j = 0; j < 8; j++) {
            int col = n0 + wn * 64 + j * 8 + 2 * t;
            float b0v = 0.0f, b1v = 0.0f;
            if (do_bias) { b0v = bias[col]; b1v = bias[col + 1]; }
            float v00 = acc[i][j][0] + b0v, v01 = acc[i][j][1] + b1v;
            float v10 = acc[i][j][2] + b0v, v11 = acc[i][j][3] + b1v;
            if (do_gelu) {
                v00 = rtf_f(gelu_tanh(v00)); v01 = rtf_f(gelu_tanh(v01));
                v10 = rtf_f(gelu_tanh(v10)); v11 = rtf_f(gelu_tanh(v11));
            }
            float* p0 = &C[(size_t)row0 * N + col];
            float* p1 = &C[(size_t)(row0 + 8) * N + col];
            if (do_acc) {
                float2 o0 = *(float2*)p0;
                float2 o1 = *(float2*)p1;
                v00 += o0.x; v01 += o0.y;
                v10 += o1.x; v11 += o1.y;
            }
            *(float2*)p0 = make_float2(v00, v01);
            *(float2*)p1 = make_float2(v10, v11);
        }
    }
}

// ------------------------------------------------------------------
// Rotary on fused qkvg buffer (q at col 0, k at col DD), row stride 6144
// ------------------------------------------------------------------
__global__ void rotary_kernel(float* __restrict__ qkvg,
                              const float* __restrict__ sint,
                              const float* __restrict__ cost) {
    int idx = blockIdx.x * blockDim.x + threadIdx.x;
    if (idx >= BB * SS * HH * 32) return;
    int i  = idx & 31;
    int t  = idx >> 5;
    int h  = t & 15;
    int bs = t >> 4;
    int s  = bs & (SS - 1);
    float sn = sint[s * 32 + i];
    float cs = cost[s * 32 + i];
    size_t base = (size_t)bs * NQKVG + h * 64 + 2 * i;
    float q0 = qkvg[base], q1 = qkvg[base + 1];
    qkvg[base]     = q0 * cs - q1 * sn;
    qkvg[base + 1] = q1 * cs + q0 * sn;
    size_t kb = base + DD;
    float k0 = qkvg[kb], k1 = qkvg[kb + 1];
    qkvg[kb]     = (k0 * cs - k1 * sn) * 0.125f;
    qkvg[kb + 1] = (k1 * cs + k0 * sn) * 0.125f;
}

// ------------------------------------------------------------------
// Tensorized retention attention (tf32 mma for QK^T and S@V).
// Block = (nt, h, b): 64 query rows. 8 warps.
// QK warp tile 16x32; PV warp tile 16x64.
// Layouts: Qs/St [row][k] stride 68 (A-frag, 64 cols + 4 pad, 68%32==4
// -> conflict-free); KsT [k][key] stride 72, Vs [m][c] stride 136.
// ------------------------------------------------------------------
#define QST 68                          // Qs/St row stride
#define ATT_KS  (64*QST)
#define ATT_VS  (ATT_KS + 64*72)
#define ATT_ST  (ATT_VS + 64*136)
#define ATT_AB  (ATT_ST + 64*QST)
#define ATT_CR  (ATT_AB + 64)
#define ATT_RED (ATT_CR + 64)
#define ATTN_SHMEM ((ATT_RED + 128) * 4)   // 89,088 B -> 2 CTAs/SM

__global__ __launch_bounds__(256, 2)
void attn_kernel(const float* __restrict__ qkvg, float* __restrict__ outp) {
    extern __shared__ float sh[];
    float* Qs    = sh;                 // [64][68]
    float* KsT   = sh + ATT_KS;        // [64 k][72]
    float* Vs    = sh + ATT_VS;        // [64 m][136]
    float* St    = sh + ATT_ST;        // [64][68]
    float* absum = sh + ATT_AB;        // [64]
    float* crow  = sh + ATT_CR;        // [64]
    float* red   = sh + ATT_RED;       // [64][2]

    int tid = threadIdx.x;
    int nt = blockIdx.x, h = blockIdx.y, b = blockIdx.z;
    int n0 = nt * 64;
    int wid = tid >> 5, lane = tid & 31;
    int g = lane >> 2, t = lane & 3;
    int wr  = (wid & 3) * 16;     // warp row offset
    int wcS = (wid >> 2) * 32;    // QK col offset
    int wcO = (wid >> 2) * 64;    // PV col offset

    double gamma_d = 1.0 - exp2((double)(-5 - h));
    float lg2g = (float)log2(gamma_d);

    // Load Q tile (row-major, tf32-rounded)
    #pragma unroll
    for (int qq = 0; qq < 4; qq++) {
        int p = tid + qq * 256;
        int r = p >> 4, c4 = (p & 15) * 4;
        float4 t4 = *(const float4*)&qkvg[((size_t)(b * SS + n0 + r)) * NQKVG + h * 64 + c4];
        t4.x = rtf_f(t4.x); t4.y = rtf_f(t4.y); t4.z = rtf_f(t4.z); t4.w = rtf_f(t4.w);
        *(float4*)&Qs[r * QST + c4] = t4;
    }
    if (tid < 64) {
        absum[tid] = 0.0f;
        int n = n0 + tid;
        double ssum = (1.0 - pow(gamma_d, (double)(n + 1))) / (1.0 - gamma_d);
        crow[tid] = (float)(1.0 / sqrt(ssum));
    }

    float oa[8][4];
    #pragma unroll
    for (int j = 0; j < 8; j++)
        #pragma unroll
        for (int r = 0; r < 4; r++) oa[j][r] = 0.0f;

    int lr0 = wr + g, lr1 = lr0 + 8;   // local query rows

    for (int mt = 0; mt <= nt; mt++) {
        int m0 = mt * 64;
        __syncthreads();
        // K tile: KsT[k][key], rounded
        #pragma unroll
        for (int qq = 0; qq < 4; qq++) {
            int p = tid + qq * 256;
            int m = p >> 4, c4 = (p & 15) * 4;
            float4 t4 = *(const float4*)&qkvg[((size_t)(b * SS + m0 + m)) * NQKVG + DD + h * 64 + c4];
            KsT[(c4 + 0) * 72 + m] = rtf_f(t4.x);
            KsT[(c4 + 1) * 72 + m] = rtf_f(t4.y);
            KsT[(c4 + 2) * 72 + m] = rtf_f(t4.z);
            KsT[(c4 + 3) * 72 + m] = rtf_f(t4.w);
        }
        // V tile: Vs[m][c], rounded
        #pragma unroll
        for (int qq = 0; qq < 8; qq++) {
            int p = tid + qq * 256;
            int m = p >> 5, c4 = (p & 31) * 4;
            float4 t4 = *(const float4*)&qkvg[((size_t)(b * SS + m0 + m)) * NQKVG + 2 * DD + h * 128 + c4];
            t4.x = rtf_f(t4.x); t4.y = rtf_f(t4.y); t4.z = rtf_f(t4.z); t4.w = rtf_f(t4.w);
            *(float4*)&Vs[m * 136 + c4] = t4;
        }
        __syncthreads();

        // ---- QK^T: s[j][4], warp tile 16x32, k=64
        float s[4][4];
        #pragma unroll
        for (int j = 0; j < 4; j++)
            #pragma unroll
            for (int r = 0; r < 4; r++) s[j][r] = 0.0f;
        #pragma unroll
        for (int ks = 0; ks < 8; ks++) {
            int kk = ks * 8;
            uint32_t a[4];
            a[0] = __float_as_uint(Qs[lr0 * QST + kk + t]);
            a[1] = __float_as_uint(Qs[lr1 * QST + kk + t]);
            a[2] = __float_as_uint(Qs[lr0 * QST + kk + t + 4]);
            a[3] = __float_as_uint(Qs[lr1 * QST + kk + t + 4]);
            #pragma unroll
            for (int j = 0; j < 4; j++) {
                uint32_t bb[2];
                int cb = wcS + j * 8 + g;
                bb[0] = __float_as_uint(KsT[(kk + t) * 72 + cb]);
                bb[1] = __float_as_uint(KsT[(kk + t + 4) * 72 + cb]);
                mma_tf32(s[j], a, bb);
            }
        }

        // ---- decay + mask + crow, write St (rounded), abs partials
        int gr0 = n0 + lr0, gr1 = n0 + lr1;   // global query indices
        float c0f = crow[lr0], c1f = crow[lr1];
        float pr0 = 0.0f, pr1 = 0.0f;
        #pragma unroll
        for (int j = 0; j < 4; j++) {
            int mc = m0 + wcS + j * 8 + 2 * t;
            float v00 = (mc     <= gr0) ? rtf_f(s[j][0] * exp2f((float)(gr0 - mc)     * lg2g) * c0f) : 0.0f;
            float v01 = (mc + 1 <= gr0) ? rtf_f(s[j][1] * exp2f((float)(gr0 - mc - 1) * lg2g) * c0f) : 0.0f;
            float v10 = (mc     <= gr1) ? rtf_f(s[j][2] * exp2f((float)(gr1 - mc)     * lg2g) * c1f) : 0.0f;
            float v11 = (mc + 1 <= gr1) ? rtf_f(s[j][3] * exp2f((float)(gr1 - mc - 1) * lg2g) * c1f) : 0.0f;
            int lc = wcS + j * 8 + 2 * t;
            *(float2*)&St[lr0 * QST + lc] = make_float2(v00, v01);
            *(float2*)&St[lr1 * QST + lc] = make_float2(v10, v11);
            pr0 += fabsf(v00) + fabsf(v01);
            pr1 += fabsf(v10) + fabsf(v11);
        }
        pr0 += __shfl_xor_sync(0xffffffffu, pr0, 1);
        pr0 += __shfl_xor_sync(0xffffffffu, pr0, 2);
        pr1 += __shfl_xor_sync(0xffffffffu, pr1, 1);
        pr1 += __shfl_xor_sync(0xffffffffu, pr1, 2);
        if (t == 0) {
            atomicAdd(&absum[lr0], pr0);
            atomicAdd(&absum[lr1], pr1);
        }
        __syncthreads();

        // ---- PV: oa += St @ V, warp tile 16x64, k=64
        #pragma unroll
        for (int ks = 0; ks < 8; ks++) {
            int kk = ks * 8;
            uint32_t a[4];
            a[0] = __float_as_uint(St[lr0 * QST + kk + t]);
            a[1] = __float_as_uint(St[lr1 * QST + kk + t]);
            a[2] = __float_as_uint(St[lr0 * QST + kk + t + 4]);
            a[3] = __float_as_uint(St[lr1 * QST + kk + t + 4]);
            #pragma unroll
            for (int j = 0; j < 8; j++) {
                uint32_t bb[2];
                int cb = wcO + j * 8 + g;
                bb[0] = __float_as_uint(Vs[(kk + t) * 136 + cb]);
                bb[1] = __float_as_uint(Vs[(kk + t + 4) * 136 + cb]);
                mma_tf32(oa[j], a, bb);
            }
        }
    }
    __syncthreads();

    // ---- finalize: L1 clip, RMS over DV, SiLU gate
    float inv0 = 1.0f / fmaxf(1.0f, absum[lr0]);
    float inv1 = 1.0f / fmaxf(1.0f, absum[lr1]);
    float ssq0 = 0.0f, ssq1 = 0.0f;
    #pragma unroll
    for (int j = 0; j < 8; j++) {
        oa[j][0] *= inv0; oa[j][1] *= inv0;
        oa[j][2] *= inv1; oa[j][3] *= inv1;
        ssq0 += oa[j][0] * oa[j][0] + oa[j][1] * oa[j][1];
        ssq1 += oa[j][2] * oa[j][2] + oa[j][3] * oa[j][3];
    }
    ssq0 += __shfl_xor_sync(0xffffffffu, ssq0, 1);
    ssq0 += __shfl_xor_sync(0xffffffffu, ssq0, 2);
    ssq1 += __shfl_xor_sync(0xffffffffu, ssq1, 1);
    ssq1 += __shfl_xor_sync(0xffffffffu, ssq1, 2);
    int half = wid >> 2;
    if (t == 0) {
        red[lr0 * 2 + half] = ssq0;
        red[lr1 * 2 + half] = ssq1;
    }
    __syncthreads();
    float sc0 = rsqrtf((red[lr0 * 2] + red[lr0 * 2 + 1]) * (1.0f / 128.0f) + 1e-6f);
    float sc1 = rsqrtf((red[lr1 * 2] + red[lr1 * 2 + 1]) * (1.0f / 128.0f) + 1e-6f);
    size_t gg0 = ((size_t)(b * SS + n0 + lr0)) * NQKVG + 4 * DD + h * 128;
    size_t gg1 = ((size_t)(b * SS + n0 + lr1)) * NQKVG + 4 * DD + h * 128;
    size_t ob0 = ((size_t)(b * SS + n0 + lr0)) * (2 * DD) + h * 128;
    size_t ob1 = ((size_t)(b * SS + n0 + lr1)) * (2 * DD) + h * 128;
    #pragma unroll
    for (int j = 0; j < 8; j++) {
        int c = wcO + j * 8 + 2 * t;
        float2 gv0 = *(const float2*)&qkvg[gg0 + c];
        float2 gv1 = *(const float2*)&qkvg[gg1 + c];
        float s00 = gv0.x / (1.0f + expf(-gv0.x));
        float s01 = gv0.y / (1.0f + expf(-gv0.y));
        float s10 = gv1.x / (1.0f + expf(-gv1.x));
        float s11 = gv1.y / (1.0f + expf(-gv1.y));
        *(float2*)&outp[ob0 + c] = make_float2(rtf_f(s00 * (oa[j][0] * sc0)),
                                               rtf_f(s01 * (oa[j][1] * sc0)));
        *(float2*)&outp[ob1 + c] = make_float2(rtf_f(s10 * (oa[j][2] * sc1)),
                                               rtf_f(s11 * (oa[j][3] * sc1)));
    }
}

// ------------------------------------------------------------------
// Final logits + log_softmax (V=2), one warp per token
// ------------------------------------------------------------------
__global__ void logits_kernel(const float* __restrict__ x,
                              const float* __restrict__ Wout,
                              float* __restrict__ outp) {
    int gt = blockIdx.x * blockDim.x + threadIdx.x;
    int warp = gt >> 5, lane = gt & 31;
    if (warp >= MM) return;
    const float* xr = x + (size_t)warp * DD;
    float a0 = 0.0f, a1 = 0.0f;
    for (int kk = lane; kk < DD; kk += 32) {
        float xv = xr[kk];
        a0 += xv * Wout[kk * 2 + 0];
        a1 += xv * Wout[kk * 2 + 1];
    }
    #pragma unroll
    for (int off = 16; off > 0; off >>= 1) {
        a0 += __shfl_xor_sync(0xffffffffu, a0, off);
        a1 += __shfl_xor_sync(0xffffffffu, a1, off);
    }
    if (lane == 0) {
        float mx = fmaxf(a0, a1);
        float lse = mx + logf(expf(a0 - mx) + expf(a1 - mx));
        outp[warp * 2 + 0] = a0 - lse;
        outp[warp * 2 + 1] = a1 - lse;
    }
}

// ------------------------------------------------------------------
// Orchestration
// ------------------------------------------------------------------
extern "C" void kernel_launch(void* const* d_in, const int* in_sizes, int n_in,
                              void* d_out, int out_size) {
    const int*   tokens = (const int*)  d_in[0];
    const float* emb    = (const float*)d_in[1];
    const float* Wq     = (const float*)d_in[2];
    const float* Wk     = (const float*)d_in[3];
    const float* Wv     = (const float*)d_in[4];
    const float* Wg     = (const float*)d_in[5];
    const float* Wo     = (const float*)d_in[6];
    const float* ln1_s  = (const float*)d_in[7];
    const float* ln1_b  = (const float*)d_in[8];
    const float* ln2_s  = (const float*)d_in[9];
    const float* ln2_b  = (const float*)d_in[10];
    const float* W1     = (const float*)d_in[11];
    const float* b1     = (const float*)d_in[12];
    const float* W2     = (const float*)d_in[13];
    const float* b2     = (const float*)d_in[14];
    const float* lnf_s  = (const float*)d_in[15];
    const float* lnf_b  = (const float*)d_in[16];
    const float* Wout   = (const float*)d_in[17];

    float *h, *x, *qkvg, *ao, *ffn, *sint, *cost;
    float *wqkvg, *wo, *w1, *w2;
    cudaGetSymbolAddress((void**)&h,     g_h);
    cudaGetSymbolAddress((void**)&x,     g_x);
    cudaGetSymbolAddress((void**)&qkvg,  g_qkvg);
    cudaGetSymbolAddress((void**)&ao,    g_ao);
    cudaGetSymbolAddress((void**)&ffn,   g_ffn);
    cudaGetSymbolAddress((void**)&sint,  g_sin);
    cudaGetSymbolAddress((void**)&cost,  g_cos);
    cudaGetSymbolAddress((void**)&wqkvg, g_wqkvg);
    cudaGetSymbolAddress((void**)&wo,    g_wo);
    cudaGetSymbolAddress((void**)&w1,    g_w1);
    cudaGetSymbolAddress((void**)&w2,    g_w2);

    cudaFuncSetAttribute(attn_kernel, cudaFuncAttributeMaxDynamicSharedMemorySize,
                         ATTN_SHMEM);
    cudaFuncSetAttribute(gemm_tf32_kernel, cudaFuncAttributeMaxDynamicSharedMemorySize,
                         GEMM_SMEM);

    sincos_kernel<<<(SS * 32 + 255) / 256, 256>>>(sint, cost);
    embed_kernel<<<(MM * DD + 255) / 256, 256>>>(tokens, emb, h);

    // Pre-round weights to tf32 values (2 launches, so ncu skip-5 lands on
    // the first QKVG GEMM)
    {
        int n4 = LL * DD * NQKVG / 4;
        concat_round_kernel<<<(n4 + 255) / 256, 256>>>(
            (const uint4*)Wq, (const uint4*)Wk, (const uint4*)Wv, (const uint4*)Wg,
            (uint4*)wqkvg, n4);
    }
    {
        int nWo = LL * 2 * DD * DD / 4;
        int nW1 = LL * DD * FFN_ / 4;
        int nW2 = LL * FFN_ * DD / 4;
        round3_kernel<<<(nWo + nW1 + nW2 + 255) / 256, 256>>>(
            (const uint4*)Wo, (uint4*)wo, nWo,
            (const uint4*)W1, (uint4*)w1, nW1,
            (const uint4*)W2, (uint4*)w2, nW2);
    }

    for (int l = 0; l < LL; l++) {
        const float* Wqkvg_l = wqkvg + (size_t)l * DD * NQKVG;
        const float* Wo_l = wo + (size_t)l * 2 * DD * DD;
        const float* W1_l = w1 + (size_t)l * DD * FFN_;
        const float* W2_l = w2 + (size_t)l * FFN_ * DD;
        const float* b1_l = b1 + (size_t)l * FFN_;
        const float* b2_l = b2 + (size_t)l * DD;

        // --- MSR block ---
        ln_kernel<<<MM, 256>>>(h, ln1_s + l * DD, ln1_b + l * DD, x);
        gemm_tf32_kernel<<<dim3(NQKVG / 128, MM / 128), 256, GEMM_SMEM>>>(
            x, Wqkvg_l, nullptr, qkvg, MM, NQKVG, DD, 0);
        rotary_kernel<<<(BB * SS * HH * 32 + 255) / 256, 256>>>(qkvg, sint, cost);
        attn_kernel<<<dim3(SS / 64, HH, BB), 256, ATTN_SHMEM>>>(qkvg, ao);
        gemm_tf32_kernel<<<dim3(DD / 128, MM / 128), 256, GEMM_SMEM>>>(
            ao, Wo_l, nullptr, h, MM, DD, 2 * DD, 4);

        // --- FFN block ---
        ln_kernel<<<MM, 256>>>(h, ln2_s + l * DD, ln2_b + l * DD, x);
        gemm_tf32_kernel<<<dim3(FFN_ / 128, MM / 128), 256, GEMM_SMEM>>>(
            x, W1_l, b1_l, ffn, MM, FFN_, DD, 3);
        gemm_tf32_kernel<<<dim3(DD / 128, MM / 128), 256, GEMM_SMEM>>>(
            ffn, W2_l, b2_l, h, MM, DD, FFN_, 5);
    }

    ln_kernel<<<MM, 256>>>(h, lnf_s, lnf_b, x);
    logits_kernel<<<MM * 32 / 256, 256>>>(x, Wout, (float*)d_out);
}